// round 17
// baseline (speedup 1.0000x reference)
#include <cuda_runtime.h>
#include <cuda_fp16.h>
#include <cstdint>

#define NN 131072
#define NE 4194304
#define FI 64

// ---------------- scratch (device globals: no allocation allowed) ----------
__device__ float  g_deg [NN];        // raw weighted degree (by src)
__device__ int    g_cnt [NN];        // in-degree histogram (by dst)
__device__ int    g_off [NN + 1];    // CSR row offsets (by dst)
__device__ int    g_bsum[128];       // per-scan-block totals
__device__ int    g_rank[NE];        // per-edge rank within its dst row
__device__ int2   g_edge[NE];        // CSR record: {src, weight-bits}
__device__ __half g_xh[NN * FI];     // x cast to fp16
__device__ __half g_Y1[NN * FI];     // Y1 = L x
__device__ __half g_Y2[NN * FI];     // Y2 = L Y1
__device__ __half g_Y3[NN * FI];     // Y3 = L Y2
// B operand [chunk kb][n 0..255][k 0..63] fp16, SW128-pre-swizzled (32KB/chunk)
__device__ __half g_B[4 * 256 * 64];
__device__ float  g_bias[256];       // b_x[g]+b_h[g] for gate0|gate2
__device__ int    g_any;             // static-zero init; idempotent OR across runs
                                     // g_any==0  <=>  edge_index is int64

// ---------------- edge-index access (dtype-robust, trap-proof) -------------
__device__ __forceinline__ int eidx(const void* ei, unsigned i) {
    int v;
    if (g_any == 0) v = (int)((const long long*)ei)[i];   // int64 layout
    else            v = ((const int*)ei)[i];              // int32 layout
    return v & (NN - 1);             // NN = 2^17: no-op for valid ids, trap-proof
}

// ---------------- helpers ----------------------------------------------------
__device__ __forceinline__ uint32_t smem_u32(const void* p) {
    uint32_t a;
    asm("{ .reg .u64 t; cvta.to.shared.u64 t, %1; cvt.u32.u64 %0, t; }"
        : "=r"(a) : "l"(p));
    return a;
}
#define SWZ128(o) ((o) ^ (((o) >> 3) & 0x70))

__device__ __forceinline__ void ldsm4(uint32_t& r0, uint32_t& r1, uint32_t& r2,
                                      uint32_t& r3, uint32_t addr) {
    asm volatile("ldmatrix.sync.aligned.m8n8.x4.shared.b16 {%0,%1,%2,%3}, [%4];"
                 : "=r"(r0), "=r"(r1), "=r"(r2), "=r"(r3) : "r"(addr));
}
__device__ __forceinline__ void mma16816(float* c, const uint32_t* a,
                                         uint32_t b0, uint32_t b1) {
    asm volatile("mma.sync.aligned.m16n8k16.row.col.f32.f16.f16.f32 "
                 "{%0,%1,%2,%3}, {%4,%5,%6,%7}, {%8,%9}, {%0,%1,%2,%3};"
                 : "+f"(c[0]), "+f"(c[1]), "+f"(c[2]), "+f"(c[3])
                 : "r"(a[0]), "r"(a[1]), "r"(a[2]), "r"(a[3]), "r"(b0), "r"(b1));
}
__device__ __forceinline__ void cpa16(uint32_t dst, const void* src) {
    asm volatile("cp.async.cg.shared.global [%0], [%1], 16;"
                 :: "r"(dst), "l"(src));
}
__device__ __forceinline__ float tanh_hw(float x) {
    float y;
    asm("tanh.approx.f32 %0, %1;" : "=f"(y) : "f"(x));
    return y;
}
// H = (1 - sigmoid(u)) * tanh(v), relu'd.
// 1 - sigmoid(u) = 0.5 - 0.5*tanh(u/2)  ->  2 HW tanh + 2 FMA
__device__ __forceinline__ float gru_h(float u, float v) {
    float z1 = fmaf(-0.5f, tanh_hw(0.5f * u), 0.5f);
    return fmaxf(z1 * tanh_hw(v), 0.f);
}
__device__ __forceinline__ void acc_edge(float4& acc, int2 e,
                                         const uint2* __restrict__ vin, int lh) {
    uint2 u = vin[(long)e.x * 16 + lh];
    float w = __int_as_float(e.y);
    float2 f0 = __half22float2(*reinterpret_cast<__half2*>(&u.x));
    float2 f1 = __half22float2(*reinterpret_cast<__half2*>(&u.y));
    acc.x = fmaf(w, f0.x, acc.x); acc.y = fmaf(w, f0.y, acc.y);
    acc.z = fmaf(w, f1.x, acc.z); acc.w = fmaf(w, f1.y, acc.w);
}

// ---------------- prep kernels ---------------------------------------------
// zero g_deg/g_cnt + dtype detector (blocks 0..15).
__global__ void k_detect(const int* __restrict__ w) {
    int i = blockIdx.x * 256 + threadIdx.x;      // 32768 threads = NN/4 vec4
    ((float4*)g_deg)[i] = make_float4(0.f, 0.f, 0.f, 0.f);
    ((int4*)g_cnt)[i]   = make_int4(0, 0, 0, 0);
    if (blockIdx.x < 16) {                       // 4096 samples
        int stride = (2 * (NE / 4096));
        int vv = w[(unsigned)(i * stride + 1)];
        if (__syncthreads_or(vv != 0) && threadIdx.x == 0) atomicOr(&g_any, 1);
    }
}

// x -> fp16 cast (side stream)
__global__ void k_xcast(const float4* __restrict__ x) {
    int i = blockIdx.x * 256 + threadIdx.x;      // NN*FI/4 threads
    float4 v = x[i];
    __half2 a = __floats2half2_rn(v.x, v.y);
    __half2 b = __floats2half2_rn(v.z, v.w);
    uint2 o;
    o.x = *reinterpret_cast<uint32_t*>(&a);
    o.y = *reinterpret_cast<uint32_t*>(&b);
    *reinterpret_cast<uint2*>(g_xh + (size_t)i * 4) = o;
}

// weighted degree (by src) + in-degree histogram (by dst)
__global__ void k_deg(const void* __restrict__ ei, const float2* __restrict__ ew2) {
    unsigned t = blockIdx.x * 256 + threadIdx.x;     // NE/2 threads
    unsigned e = t * 2;
    int s0, s1, d0, d1;
    if (g_any == 0) {                                // int64 layout
        const longlong2* p = (const longlong2*)ei;
        longlong2 sv = p[t];
        longlong2 dv = p[(NE / 2) + t];
        s0 = (int)sv.x & (NN - 1); s1 = (int)sv.y & (NN - 1);
        d0 = (int)dv.x & (NN - 1); d1 = (int)dv.y & (NN - 1);
    } else {
        const int2* p = (const int2*)ei;
        int2 sv = p[t];
        int2 dv = p[(NE / 2) + t];
        s0 = sv.x & (NN - 1); s1 = sv.y & (NN - 1);
        d0 = dv.x & (NN - 1); d1 = dv.y & (NN - 1);
    }
    float2 w = ew2[t];
    atomicAdd(&g_deg[s0], w.x);
    atomicAdd(&g_deg[s1], w.y);
    g_rank[e]     = atomicAdd(&g_cnt[d0], 1);
    g_rank[e + 1] = atomicAdd(&g_cnt[d1], 1);
}

// ---- parallel 2-launch exclusive scan of g_cnt -> g_off --------------------
__global__ void __launch_bounds__(1024) k_scanA() {
    __shared__ int wsum[32];
    const int tid  = threadIdx.x;
    const int lane = tid & 31;
    const int w    = tid >> 5;
    const int gid  = blockIdx.x * 1024 + tid;
    int v = g_cnt[gid];
    int x = v;
#pragma unroll
    for (int d = 1; d < 32; d <<= 1) {
        int y = __shfl_up_sync(0xffffffffu, x, d);
        if (lane >= d) x += y;
    }
    if (lane == 31) wsum[w] = x;
    __syncthreads();
    if (w == 0) {
        int s = wsum[lane];
#pragma unroll
        for (int d = 1; d < 32; d <<= 1) {
            int y = __shfl_up_sync(0xffffffffu, s, d);
            if (lane >= d) s += y;
        }
        wsum[lane] = s;
    }
    __syncthreads();
    int incl = x + (w > 0 ? wsum[w - 1] : 0);
    g_off[gid] = incl - v;                     // block-local exclusive
    if (tid == 1023) g_bsum[blockIdx.x] = incl;
}

__global__ void k_scanC() {
    __shared__ int wred[8];
    __shared__ int base_s, tot_s;
    const int tid  = threadIdx.x;
    const int lane = tid & 31;
    const int w    = tid >> 5;
    const int nb   = blockIdx.x >> 2;
    const bool last = (blockIdx.x == gridDim.x - 1);

    int bs = (tid < 128) ? g_bsum[tid] : 0;
    int vp = (tid < nb) ? bs : 0;
    int vf = last ? bs : 0;
#pragma unroll
    for (int d = 16; d > 0; d >>= 1) {
        vp += __shfl_down_sync(0xffffffffu, vp, d);
        vf += __shfl_down_sync(0xffffffffu, vf, d);
    }
    if (lane == 0) wred[w] = vp;
    __syncthreads();
    if (tid == 0) {
        int p = 0;
#pragma unroll
        for (int i = 0; i < 8; i++) p += wred[i];
        base_s = p;
    }
    __syncthreads();
    if (last && lane == 0) wred[w] = vf;
    __syncthreads();
    if (last && tid == 0) {
        int tt = 0;
#pragma unroll
        for (int i = 0; i < 8; i++) tt += wred[i];
        tot_s = tt;
    }
    int gid = blockIdx.x * 256 + tid;
    g_off[gid] += base_s;
    if (last) {
        __syncthreads();
        if (tid == 0) g_off[NN] = tot_s;
    }
}

// scatter edges into packed CSR records — NO atomics; dinv fused
__global__ void k_scatter(const void* __restrict__ ei, const float* __restrict__ ew) {
    unsigned e = blockIdx.x * 256 + threadIdx.x;
    if (e >= NE) return;
    int s = eidx(ei, e);
    int d = eidx(ei, NE + e);
    float ds = g_deg[s], dd = g_deg[d];
    float is = (ds > 0.f) ? rsqrtf(ds) : 0.f;
    float id = (dd > 0.f) ? rsqrtf(dd) : 0.f;
    float w = -is * ew[e] * id;
    unsigned pos = (unsigned)(g_off[d] + g_rank[e]) & (NE - 1);  // trap-proof
    g_edge[pos] = make_int2(s, __float_as_int(w));
}

// Pack B (side stream): reparametrized Chebyshev weights, [n][k], fp16, SW128.
//   B0 = W0 - W2 ; B1 = W1 - 3*W3 ; B2 = 2*W2 ; B3 = 4*W3
__global__ void k_pack(const float* __restrict__ Wx, const float* __restrict__ bx,
                       const float* __restrict__ bh) {
    int i = blockIdx.x * 256 + threadIdx.x;   // 65536 total
    int kb = i >> 14, n = (i >> 6) & 255, kk = i & 63;
    int g  = (n < 128) ? 0 : 2;
    int jj = n & 127;
    const size_t base = (size_t)g * 4 * 64 * 128 + (size_t)kk * 128 + jj;
    const size_t kstep = (size_t)64 * 128;
    float w;
    if      (kb == 0) w = Wx[base]             - Wx[base + 2 * kstep];
    else if (kb == 1) w = Wx[base + kstep]     - 3.f * Wx[base + 3 * kstep];
    else if (kb == 2) w = 2.f * Wx[base + 2 * kstep];
    else              w = 4.f * Wx[base + 3 * kstep];
    uint32_t off = SWZ128((uint32_t)(n * 128 + kk * 2));
    g_B[(uint32_t)kb * 16384 + (off >> 1)] = __float2half(w);
    if (kb == 0 && kk == 0) g_bias[n] = bx[g * 128 + jj] + bh[g * 128 + jj];
}

// ---------------- SpMM gather (fp16 rows), PERSISTENT grid ------------------
// Each warp strides over nodes; per-node math identical to proven version.
__global__ void __launch_bounds__(256)
k_spmm(const uint2* __restrict__ vin, uint2* __restrict__ vout) {
    const int lane = threadIdx.x & 31;
    const int lh   = lane & 15;
    const int half = lane >> 4;
    const int gw   = blockIdx.x * 8 + (threadIdx.x >> 5);
    const int wstep = gridDim.x * 8;

    for (int node = gw; node < NN; node += wstep) {
        const int beg = g_off[node];
        const int end = g_off[node + 1];
        float4 acc = make_float4(0.f, 0.f, 0.f, 0.f);
        int i = beg + half;
        for (; i + 6 < end; i += 8) {        // 4 edges per half-warp in flight
            int2 e0 = g_edge[i];
            int2 e1 = g_edge[i + 2];
            int2 e2 = g_edge[i + 4];
            int2 e3 = g_edge[i + 6];
            acc_edge(acc, e0, vin, lh);
            acc_edge(acc, e1, vin, lh);
            acc_edge(acc, e2, vin, lh);
            acc_edge(acc, e3, vin, lh);
        }
        for (; i < end; i += 2) {
            int2 e0 = g_edge[i];
            acc_edge(acc, e0, vin, lh);
        }
        acc.x += __shfl_xor_sync(0xffffffffu, acc.x, 16);
        acc.y += __shfl_xor_sync(0xffffffffu, acc.y, 16);
        acc.z += __shfl_xor_sync(0xffffffffu, acc.z, 16);
        acc.w += __shfl_xor_sync(0xffffffffu, acc.w, 16);

        if (half == 0) {
            __half2 h01 = __floats2half2_rn(acc.x, acc.y);
            __half2 h23 = __floats2half2_rn(acc.z, acc.w);
            uint2 o;
            o.x = *reinterpret_cast<uint32_t*>(&h01);
            o.y = *reinterpret_cast<uint32_t*>(&h23);
            vout[(long)node * 16 + lh] = o;
        }
    }
}

// ---------------- mma.sync GEMM, PERSISTENT grid + GRU epilogue -------------
// A fp16, B fp16; fp32 accum. cp.async double-buffered per tile.
// SMEM: [0..1024) row-reduce; A ping-pong @1024 (2x16KB); B ping-pong @33792
// (2x32KB). Total 99328 B. 148 resident CTAs loop over 1024 row tiles.
#define SM_A0  1024
#define SM_B0  33792
#define SM_DYN 99328
#define GEMM_CTAS 148

__global__ void __launch_bounds__(256, 1)
k_gemm_mma(const float* __restrict__ Wlin, const float* __restrict__ blin,
           float* __restrict__ outbuf) {
    extern __shared__ char smem[];
    float* smf = (float*)smem;               // [0..128) rs, [128..256) dt
    const uint32_t sb  = smem_u32(smem);
    const int tid  = threadIdx.x;
    const int wid  = tid >> 5;
    const int lane = tid & 31;
    const int wm   = wid & 3;
    const int wn   = wid >> 2;
    const float bl = __ldg(blin);

#pragma unroll 1
    for (int tile = blockIdx.x; tile < NN / 128; tile += GEMM_CTAS) {
        const long rowBase = (long)tile * 128;
        if (tid < 128) { smf[tid] = 0.f; smf[128 + tid] = 0.f; }

        const __half* bases[4] = { g_xh + rowBase * FI, g_Y1 + rowBase * FI,
                                   g_Y2 + rowBase * FI, g_Y3 + rowBase * FI };

        auto stage = [&](int c, int b) {
            const uint4* Asrc = (const uint4*)bases[c];
            uint32_t abase = sb + SM_A0 + (uint32_t)b * 16384;
#pragma unroll
            for (int it = 0; it < 4; it++) {
                int idx = tid + it * 256;
                int r  = idx >> 3;
                int c8 = idx & 7;
                cpa16(abase + (uint32_t)(r * 128 + ((c8 ^ (r & 7)) << 4)), Asrc + idx);
            }
            const uint4* Bsrc = (const uint4*)(g_B + (size_t)c * 16384);
            uint32_t bbase = sb + SM_B0 + (uint32_t)b * 32768;
#pragma unroll
            for (int it = 0; it < 8; it++) {
                int idx = tid + it * 256;
                cpa16(bbase + (uint32_t)idx * 16, Bsrc + idx);
            }
            asm volatile("cp.async.commit_group;");
        };

        float acc[2][16][4];
#pragma unroll
        for (int mt = 0; mt < 2; mt++)
#pragma unroll
            for (int t = 0; t < 16; t++)
#pragma unroll
                for (int q = 0; q < 4; q++) acc[mt][t][q] = 0.f;

        stage(0, 0);

#pragma unroll 1
        for (int c = 0; c < 4; c++) {
            const int cur = c & 1;
            if (c < 3) {
                stage(c + 1, cur ^ 1);
                asm volatile("cp.async.wait_group 1;");
            } else {
                asm volatile("cp.async.wait_group 0;");
            }
            __syncthreads();

            const uint32_t Aoff = SM_A0 + (uint32_t)cur * 16384;
            const uint32_t Boff = SM_B0 + (uint32_t)cur * 32768;
#pragma unroll
            for (int ks = 0; ks < 4; ks++) {
                uint32_t a[2][4];
#pragma unroll
                for (int mt = 0; mt < 2; mt++) {
                    int r = wm * 32 + mt * 16 + (lane & 15);
                    int g = 2 * ks + (lane >> 4);
                    uint32_t ad = sb + Aoff + (uint32_t)(r * 128 + ((g ^ (r & 7)) << 4));
                    ldsm4(a[mt][0], a[mt][1], a[mt][2], a[mt][3], ad);
                }
#pragma unroll
                for (int p = 0; p < 8; p++) {
                    int tix = (p < 4) ? (2 * p) : (8 + 2 * (p - 4));
                    int ntb = wn * 8 + ((p < 4) ? (2 * p) : (16 + 2 * (p - 4)));
                    int n = ntb * 8 + (lane & 7) + ((lane >> 4) << 3);
                    int g = 2 * ks + ((lane >> 3) & 1);
                    uint32_t bd = sb + Boff + (uint32_t)(n * 128 + ((g ^ (n & 7)) << 4));
                    uint32_t b0, b1, b2, b3;
                    ldsm4(b0, b1, b2, b3, bd);
                    mma16816(acc[0][tix],     a[0], b0, b1);
                    mma16816(acc[1][tix],     a[1], b0, b1);
                    mma16816(acc[0][tix + 1], a[0], b2, b3);
                    mma16816(acc[1][tix + 1], a[1], b2, b3);
                }
            }
            __syncthreads();
        }

        // ---- GRU epilogue (HW tanh) ----------------------------------------
#pragma unroll
        for (int mt = 0; mt < 2; mt++) {
            float rs0 = 0.f, dt0 = 0.f, rs1 = 0.f, dt1 = 0.f;
#pragma unroll
            for (int i = 0; i < 8; i++) {
                int j0 = wn * 64 + i * 8 + 2 * (lane & 3);
                float bu0 = __ldg(g_bias + j0),       bu1 = __ldg(g_bias + j0 + 1);
                float bv0 = __ldg(g_bias + j0 + 128), bv1 = __ldg(g_bias + j0 + 129);
                float w0  = __ldg(Wlin + j0),         w1  = __ldg(Wlin + j0 + 1);
                float h00 = gru_h(acc[mt][i][0] + bu0, acc[mt][8 + i][0] + bv0);
                float h01 = gru_h(acc[mt][i][1] + bu1, acc[mt][8 + i][1] + bv1);
                float h10 = gru_h(acc[mt][i][2] + bu0, acc[mt][8 + i][2] + bv0);
                float h11 = gru_h(acc[mt][i][3] + bu1, acc[mt][8 + i][3] + bv1);
                rs0 += h00 + h01; dt0 = fmaf(h00, w0, fmaf(h01, w1, dt0));
                rs1 += h10 + h11; dt1 = fmaf(h10, w0, fmaf(h11, w1, dt1));
            }
#pragma unroll
            for (int s = 1; s < 4; s <<= 1) {
                rs0 += __shfl_xor_sync(0xffffffffu, rs0, s);
                dt0 += __shfl_xor_sync(0xffffffffu, dt0, s);
                rs1 += __shfl_xor_sync(0xffffffffu, rs1, s);
                dt1 += __shfl_xor_sync(0xffffffffu, dt1, s);
            }
            if ((lane & 3) == 0) {
                int r = wm * 32 + mt * 16 + (lane >> 2);
                atomicAdd(&smf[r],           rs0);
                atomicAdd(&smf[128 + r],     dt0);
                atomicAdd(&smf[r + 8],       rs1);
                atomicAdd(&smf[128 + r + 8], dt1);
            }
        }
        __syncthreads();
        if (tid < 128) {
            long grow = rowBase + tid;
            outbuf[grow]      = smf[128 + tid] + bl;   // out = h @ W_lin + b_lin
            outbuf[NN + grow] = sqrtf(smf[tid]);       // logits
        }
        __syncthreads();                               // smf reuse guard
    }
}

// ---------------- launch orchestration -------------------------------------
extern "C" void kernel_launch(void* const* d_in, const int* in_sizes, int n_in,
                              void* d_out, int out_size) {
    const float* x  = (const float*)d_in[0];
    const void*  ei = d_in[1];                 // int32 or int64 — detected on device
    const float* ew = (const float*)d_in[2];
    const float* Wx = (const float*)d_in[3];
    // d_in[4] = W_h : provably unused (H==0 => cheb(H,*) == bias)
    const float* bx = (const float*)d_in[5];
    const float* bh = (const float*)d_in[6];
    const float* Wl = (const float*)d_in[7];
    const float* bl = (const float*)d_in[8];
    float* out = (float*)d_out;
    (void)in_sizes; (void)n_in; (void)out_size;

    void *pXh, *pY1, *pY2, *pY3;
    cudaGetSymbolAddress(&pXh, g_xh);
    cudaGetSymbolAddress(&pY1, g_Y1);
    cudaGetSymbolAddress(&pY2, g_Y2);
    cudaGetSymbolAddress(&pY3, g_Y3);

    cudaFuncSetAttribute(k_gemm_mma, cudaFuncAttributeMaxDynamicSharedMemorySize, SM_DYN);

    // fork/join side stream (fresh per call: deterministic DAG, no statics)
    cudaStream_t s1;
    cudaEvent_t eFork, eJoin;
    cudaStreamCreateWithFlags(&s1, cudaStreamNonBlocking);
    cudaEventCreateWithFlags(&eFork, cudaEventDisableTiming);
    cudaEventCreateWithFlags(&eJoin, cudaEventDisableTiming);

    // ---- main stream: detect(+zero) -> deg -> scanA -> scanC -> scatter
    k_detect<<<128, 256>>>((const int*)ei);
    cudaEventRecord(eFork, 0);
    cudaStreamWaitEvent(s1, eFork, 0);

    // ---- side stream (independent of edge pipeline): xcast, pack
    k_xcast<<<(NN * FI / 4) / 256, 256, 0, s1>>>((const float4*)x);
    k_pack <<<256, 256, 0, s1>>>(Wx, bx, bh);
    cudaEventRecord(eJoin, s1);

    k_deg    <<<(NE / 2) / 256, 256>>>(ei, (const float2*)ew);
    k_scanA  <<<NN / 1024, 1024>>>();
    k_scanC  <<<NN / 256, 256>>>();
    k_scatter<<<NE / 256, 256>>>(ei, ew);  // dinv fused (rsqrt inline)

    // join before SpMM (needs g_xh) / GEMM (needs g_B)
    cudaStreamWaitEvent(0, eJoin, 0);

    // ---- power basis: Y1 = L x ; Y2 = L Y1 ; Y3 = L Y2   (persistent grids)
    k_spmm<<<1184, 256>>>((const uint2*)pXh, (uint2*)pY1);
    k_spmm<<<1184, 256>>>((const uint2*)pY1, (uint2*)pY2);
    k_spmm<<<1184, 256>>>((const uint2*)pY2, (uint2*)pY3);

    // ---- fused mma.sync GEMM + GRU + head (persistent 148 CTAs)
    k_gemm_mma<<<GEMM_CTAS, 256, SM_DYN>>>(Wl, bl, out);
}